// round 5
// baseline (speedup 1.0000x reference)
#include <cuda_runtime.h>
#include <cstdint>

#define BS      16
#define CIN     32
#define COUT    64
#define OUT_DIM 1024
#define P_BLK   2
#define THREADS 128                 // pp(2) x bg(4) x og(16)
#define NBLOCKS (OUT_DIM / P_BLK)   // 512

// smem x tile, float4 granules: per c, 32 granules (pp:2 x b:16), granule =
// one batch's k-quad for one patch. Logical (pp,b) stored at
//   H = pp*16 + (b>>2)*4 + ((b&3) ^ (2*pp + (b>>3)))
// => consumer LDS.128 phases hit 8 distinct 16B chunks (conflict-free).
// c-stride padded to 33 float4 (528B) to rotate chunks across c.
#define CSTRIDE4 33
#define SMEM_F4  (CIN * CSTRIDE4)   // 1056 float4 = 16.9 KB

typedef unsigned long long ull;

__global__ __launch_bounds__(THREADS, 4)
void lc1d_v3(const float* __restrict__ x,
             const float* __restrict__ w,
             float* __restrict__ out)
{
    __shared__ __align__(16) float4 xs4[SMEM_F4];

    const int tid = threadIdx.x;
    const int blk = blockIdx.x;

    // ---------------- producer: stage x tile (8 float4 per thread) ----------
    {
        const float4* x4 = reinterpret_cast<const float4*>(x);
        #pragma unroll
        for (int it = 0; it < 8; ++it) {
            int i  = it * THREADS + tid;     // 0..1023
            int pp = i & 1;
            int c  = (i >> 1) & 31;
            int b  = i >> 6;                 // 0..15
            float4 v = x4[(size_t)(b * CIN + c) * OUT_DIM + (size_t)blk * P_BLK + pp];
            int s = 2 * pp + (b >> 3);
            int H = pp * 16 + (b >> 2) * 4 + ((b & 3) ^ s);
            xs4[c * CSTRIDE4 + H] = v;
        }
    }
    __syncthreads();

    // ---------------- consumer ----------------
    const int pp = tid & 1;
    const int bg = (tid >> 1) & 3;     // batches 4*bg .. 4*bg+3
    const int og = tid >> 3;           // o = 4*og + i, i in [0,4)
    const int p  = blk * P_BLK + pp;

    uint32_t sbase;
    asm("{ .reg .u64 t; cvta.to.shared.u64 t, %1; cvt.u32.u64 %0, t; }"
        : "=r"(sbase) : "l"(xs4));

    // 4 swizzled shared addresses, one per owned batch; advance 528B per c.
    uint32_t a[4];
    {
        const int s = 2 * pp + (bg >> 1);
        #pragma unroll
        for (int q = 0; q < 4; ++q)
            a[q] = sbase + 16u * (uint32_t)(pp * 16 + bg * 4 + (q ^ s));
    }

    // acc[i*4+q]: o = 4*og+i, b = 4*bg+q; f32x2 lanes hold (k01, k23) partials
    ull acc[16];
    #pragma unroll
    for (int t = 0; t < 16; ++t) acc[t] = 0ULL;

    // w as 16B k-quads: index = (o*CIN + c)*1024 + p
    const ulonglong2* wp = reinterpret_cast<const ulonglong2*>(w)
                         + (size_t)(og * 4) * CIN * 1024 + (size_t)blk * P_BLK + pp;

    // double-buffered w: 4 o's x {lo=(k0,k1), hi=(k2,k3)}
    ull wlo[2][4], whi[2][4];
    #pragma unroll
    for (int i = 0; i < 4; ++i) {
        ulonglong2 t = wp[(size_t)i * (CIN * 1024)];
        wlo[0][i] = t.x; whi[0][i] = t.y;
    }

    #pragma unroll 2
    for (int c = 0; c < CIN; ++c) {
        const int cur = c & 1, nxt = cur ^ 1;
        if (c + 1 < CIN) {
            const ulonglong2* wn = wp + (size_t)(c + 1) * 1024;
            #pragma unroll
            for (int i = 0; i < 4; ++i) {
                ulonglong2 t = wn[(size_t)i * (CIN * 1024)];
                wlo[nxt][i] = t.x; whi[nxt][i] = t.y;
            }
        }

        // x for 4 owned batches
        ull xlo[4], xhi[4];
        #pragma unroll
        for (int q = 0; q < 4; ++q) {
            asm("ld.shared.v2.u64 {%0, %1}, [%2];"
                : "=l"(xlo[q]), "=l"(xhi[q]) : "r"(a[q]));
            a[q] += CSTRIDE4 * 16;
        }

        #pragma unroll
        for (int i = 0; i < 4; ++i) {
            const ull wl = wlo[cur][i], wh = whi[cur][i];
            #pragma unroll
            for (int q = 0; q < 4; ++q) {
                asm("fma.rn.f32x2 %0, %1, %2, %0;"
                    : "+l"(acc[i * 4 + q]) : "l"(xlo[q]), "l"(wl));
                asm("fma.rn.f32x2 %0, %1, %2, %0;"
                    : "+l"(acc[i * 4 + q]) : "l"(xhi[q]), "l"(wh));
            }
        }
    }

    // ---------------- epilogue: fold k-lanes, scale, store ----------------
    const float sc = 0.17677669529663687f;   // 1/sqrt(32)
    #pragma unroll
    for (int i = 0; i < 4; ++i) {
        const int o = og * 4 + i;
        #pragma unroll
        for (int q = 0; q < 4; ++q) {
            float lo, hi;
            asm("mov.b64 {%0, %1}, %2;" : "=f"(lo), "=f"(hi) : "l"(acc[i * 4 + q]));
            const int b = bg * 4 + q;
            out[(size_t)b * (COUT * OUT_DIM) + (size_t)o * OUT_DIM + p] = (lo + hi) * sc;
        }
    }
}

extern "C" void kernel_launch(void* const* d_in, const int* in_sizes, int n_in,
                              void* d_out, int out_size)
{
    const float* x = (const float*)d_in[0];   // [16, 32, 4096]
    const float* w = (const float*)d_in[1];   // [64, 32, 4096]
    float* out = (float*)d_out;               // [16, 64, 1024]
    (void)in_sizes; (void)n_in; (void)out_size;

    lc1d_v3<<<NBLOCKS, THREADS>>>(x, w, out);
}